// round 16
// baseline (speedup 1.0000x reference)
#include <cuda_runtime.h>
#include <math.h>
#include <stdint.h>

#define Nn    4096
#define DIMS  64
#define NB1   1024
#define SH1   16
#define NB2   131072
#define KB    0xC0800000u
#define SPAN1 0x04000000u
#define R_LO 8390655u
#define R_HI 8390656u
#define TNT   32
#define TILES 528
#define TSZ   16384

__device__ float    g_D[2][TILES*TSZ];
__device__ unsigned g_hist1[2][NB1];
__device__ unsigned g_below1[2];
__device__ unsigned g_hist2[2][NB2];
__device__ unsigned g_C[2][1024];
__device__ unsigned g_below2[2];
__device__ double   g_rowd[2][Nn];
__device__ double   g_totd[2];
__device__ double   g_part[5][TILES];

__device__ __forceinline__ unsigned f2k(float f){
    unsigned u = __float_as_uint(f);
    return (u & 0x80000000u) ? ~u : (u | 0x80000000u);
}
__device__ __forceinline__ float k2f(unsigned k){
    unsigned u = (k & 0x80000000u) ? (k & 0x7FFFFFFFu) : ~k;
    return __uint_as_float(u);
}
__device__ __forceinline__ void tri_decode(int q, int &bi, int &bj){
    int b = (int)((65.0 - sqrt(65.0*65.0 - 8.0*(double)q))*0.5);
    if (b > TNT-1) b = TNT-1;
    while (b*(2*TNT+1-b)/2 > q) b--;
    while ((b+1)*(2*TNT+1-(b+1))/2 <= q) b++;
    bi = b; bj = b + (q - b*(2*TNT+1-b)/2);
}

__device__ __forceinline__ void fma2(unsigned long long &d,
                                     unsigned long long a,
                                     unsigned long long b){
    asm("fma.rn.f32x2 %0, %1, %2, %3;" : "=l"(d) : "l"(a), "l"(b), "l"(d));
}
__device__ __forceinline__ unsigned long long dup2(float x){
    unsigned long long r;
    asm("mov.b64 %0, {%1, %1};" : "=l"(r) : "r"(__float_as_uint(x)));
    return r;
}

// magic-number exp2 for x in (-120, 0]; deg-7 Taylor on [-0.5,0.5], err ~5e-9
__device__ __forceinline__ float exp2m(float x){
    float t = x + 12582912.0f;
    int   r = __float_as_int(t) - 0x4B400000;
    float f = x - (t - 12582912.0f);
    float p = 1.5252734e-5f;
    p = fmaf(p, f, 1.5403530e-4f);
    p = fmaf(p, f, 1.3333558e-3f);
    p = fmaf(p, f, 9.6181291e-3f);
    p = fmaf(p, f, 5.5504109e-2f);
    p = fmaf(p, f, 2.4022651e-1f);
    p = fmaf(p, f, 6.9314718e-1f);
    p = fmaf(p, f, 1.0f);
    return p * __int_as_float((r+127)<<23);
}

__device__ __forceinline__ unsigned blockScanU(unsigned v, unsigned* ws){
    int lane = threadIdx.x & 31, warp = threadIdx.x >> 5;
    __syncthreads();
    if (threadIdx.x < 32) ws[threadIdx.x] = 0u;
    __syncthreads();
    unsigned x = v;
    #pragma unroll
    for (int off=1; off<32; off<<=1){
        unsigned y = __shfl_up_sync(0xffffffffu, x, off);
        if (lane >= off) x += y;
    }
    if (lane==31) ws[warp] = x;
    __syncthreads();
    if (warp==0){
        unsigned w = ws[lane];
        #pragma unroll
        for (int off=1; off<32; off<<=1){
            unsigned y = __shfl_up_sync(0xffffffffu, w, off);
            if (lane >= off) w += y;
        }
        ws[lane] = w;
    }
    __syncthreads();
    unsigned base = warp ? ws[warp-1] : 0u;
    return base + x;
}

// ---- distance tiles: column-paired f32x2 GEMM + fused norms + fused hist ---
__global__ void __launch_bounds__(256) k_dist(const float* __restrict__ X,
                                              const float* __restrict__ Y){
    const int mat = blockIdx.y;
    const float* A = mat ? Y : X;
    float* Dt = g_D[mat] + (size_t)blockIdx.x * TSZ;
    int bi, bj; tri_decode(blockIdx.x, bi, bj);
    int i0 = bi*128, j0 = bj*128;
    __shared__ float As[128][33];
    __shared__ float Bsk[32][130];
    __shared__ float Gi[128], Gj[128];
    __shared__ unsigned hb[NB1+1];
    int t = threadIdx.x;
    int tx = t & 15, ty = t >> 4;
    for (int b=t; b<NB1+1; b+=256) hb[b]=0u;

    unsigned long long acc2[8][4];
    #pragma unroll
    for (int a=0;a<8;a++)
        #pragma unroll
        for (int b=0;b<4;b++) acc2[a][b]=0ull;
    float nrm = 0.0f;

    for (int kk=0; kk<64; kk+=32){
        __syncthreads();
        #pragma unroll
        for (int it=0; it<4; it++){
            int l = t + it*256;
            int r = l >> 3, c4 = l & 7;
            float4 va = *(const float4*)&A[(i0+r)*DIMS + kk + c4*4];
            As[r][c4*4+0]=va.x; As[r][c4*4+1]=va.y; As[r][c4*4+2]=va.z; As[r][c4*4+3]=va.w;
            float4 vb = *(const float4*)&A[(j0+r)*DIMS + kk + c4*4];
            Bsk[c4*4+0][r]=vb.x; Bsk[c4*4+1][r]=vb.y; Bsk[c4*4+2][r]=vb.z; Bsk[c4*4+3][r]=vb.w;
        }
        __syncthreads();
        {
            float s = 0.0f;
            if (t < 128){
                #pragma unroll 8
                for (int k=0;k<32;k++){ float v = As[t][k]; s += v*v; }
            } else {
                int r = t - 128;
                #pragma unroll 8
                for (int k=0;k<32;k++){ float v = Bsk[k][r]; s += v*v; }
            }
            nrm += s;
        }
        #pragma unroll 8
        for (int k=0;k<32;k++){
            unsigned long long ad[8], bp[4];
            #pragma unroll
            for (int a=0;a<8;a++) ad[a] = dup2(As[ty+16*a][k]);
            #pragma unroll
            for (int b=0;b<4;b++)
                bp[b] = *(const unsigned long long*)&Bsk[k][2*tx + 32*b];
            #pragma unroll
            for (int a=0;a<8;a++){
                fma2(acc2[a][0], ad[a], bp[0]);
                fma2(acc2[a][1], ad[a], bp[1]);
                fma2(acc2[a][2], ad[a], bp[2]);
                fma2(acc2[a][3], ad[a], bp[3]);
            }
        }
    }
    if (t < 128) Gi[t] = nrm; else Gj[t-128] = nrm;
    __syncthreads();

    unsigned w = (bi==bj) ? 1u : 2u;
    float gi[8];
    #pragma unroll
    for (int a=0;a<8;a++) gi[a] = Gi[ty+16*a];
    #pragma unroll
    for (int a=0;a<8;a++){
        int row = ty + 16*a;
        #pragma unroll
        for (int b=0;b<4;b++){
            int col = 2*tx + 32*b;
            float dlo = __uint_as_float((unsigned)(acc2[a][b] & 0xffffffffu));
            float dhi = __uint_as_float((unsigned)(acc2[a][b] >> 32));
            float vlo = gi[a] + Gj[col]   - 2.0f*dlo;
            float vhi = gi[a] + Gj[col+1] - 2.0f*dhi;
            float2 vv; vv.x=vlo; vv.y=vhi;
            *(float2*)&Dt[row*128 + col] = vv;
            unsigned key = f2k(vlo);
            unsigned off = key - KB;
            if (off < SPAN1) atomicAdd(&hb[off>>SH1], w);
            else if (key < KB) atomicAdd(&hb[NB1], w);
            key = f2k(vhi);
            off = key - KB;
            if (off < SPAN1) atomicAdd(&hb[off>>SH1], w);
            else if (key < KB) atomicAdd(&hb[NB1], w);
        }
    }
    __syncthreads();
    for (int b=t; b<NB1; b+=256)
        if (hb[b]) atomicAdd(&g_hist1[mat][b], hb[b]);
    if (t==0 && hb[NB1]) atomicAdd(&g_below1[mat], hb[NB1]);
}

__device__ void find_windows(int mat, unsigned &W1, unsigned &W2,
                             unsigned* ws, volatile int* shB){
    int t = threadIdx.x;
    if (t==0){ shB[0]=-1; shB[1]=-1; }
    unsigned c0[4]; unsigned local=0;
    #pragma unroll
    for (int q=0;q<4;q++){ c0[q]=g_hist1[mat][t*4+q]; local+=c0[q]; }
    unsigned incl = blockScanU(local, ws);
    unsigned run = g_below1[mat] + (incl-local);
    #pragma unroll
    for (int q=0;q<4;q++){
        if (c0[q]){
            if (run<=R_LO && R_LO<run+c0[q]) shB[0]=t*4+q;
            if (run<=R_HI && R_HI<run+c0[q]) shB[1]=t*4+q;
        }
        run += c0[q];
    }
    __syncthreads();
    int b1=shB[0], b2=shB[1];
    if (b1<0) b1 = (b2>=0)? b2 : NB1/2;
    if (b2<0) b2 = b1;
    if (b2==b1) b2 = b1+1;
    W1 = KB + ((unsigned)b1 << SH1);
    W2 = KB + ((unsigned)b2 << SH1);
    __syncthreads();
}

__global__ void k_hist2(){
    int mat = blockIdx.y;
    __shared__ unsigned ws[32];
    __shared__ int shB[2];
    unsigned W1, W2;
    find_windows(mat, W1, W2, ws, shB);

    int bi, bj; tri_decode(blockIdx.x, bi, bj);
    unsigned w = (bi==bj) ? 1u : 2u;
    const float4* D4 = (const float4*)(g_D[mat] + (size_t)blockIdx.x * TSZ);
    int t = threadIdx.x;
    unsigned below = 0;
    #pragma unroll 8
    for (int it=0; it<16; it++){
        float4 d = D4[t + it*256];
        #pragma unroll
        for (int c=0;c<4;c++){
            float val = (c==0)?d.x:(c==1)?d.y:(c==2)?d.z:d.w;
            unsigned key = f2k(val);
            unsigned o1 = key - W1;
            if (o1 < 65536u){
                atomicAdd(&g_hist2[mat][o1], w);
                atomicAdd(&g_C[mat][o1>>7], w);
            } else {
                unsigned o2 = key - W2;
                if (o2 < 65536u){
                    atomicAdd(&g_hist2[mat][65536u+o2], w);
                    atomicAdd(&g_C[mat][512u+(o2>>7)], w);
                }
                else if (key < W1) below += w;
            }
        }
    }
    int lane = t & 31, warp = t >> 5;
    #pragma unroll
    for (int off=16; off; off>>=1) below += __shfl_xor_sync(0xffffffffu, below, off);
    __shared__ unsigned sb[8];
    if (lane==0) sb[warp]=below;
    __syncthreads();
    if (t==0){
        unsigned s=0;
        for (int q=0;q<8;q++) s+=sb[q];
        if (s) atomicAdd(&g_below2[mat], s);
    }
}

__device__ float compute_c(int mat, unsigned* ws, volatile int* shi,
                           volatile unsigned* shu){
    int t = threadIdx.x;
    if (t==0){ shi[0]=-1; shi[1]=-1; shi[2]=-1; shi[3]=-1; shi[4]=-1; shi[5]=-1; }
    unsigned c0[4]; unsigned loc=0;
    #pragma unroll
    for (int q=0;q<4;q++){ c0[q]=g_hist1[mat][t*4+q]; loc+=c0[q]; }
    unsigned incl = blockScanU(loc, ws);
    unsigned run = g_below1[mat] + (incl-loc);
    #pragma unroll
    for (int q=0;q<4;q++){
        if (c0[q]){
            if (run<=R_LO && R_LO<run+c0[q]) shi[0]=t*4+q;
            if (run<=R_HI && R_HI<run+c0[q]) shi[1]=t*4+q;
        }
        run += c0[q];
    }
    __syncthreads();
    int b1=shi[0], b2=shi[1];
    if (b1<0) b1=(b2>=0)?b2:NB1/2;
    if (b2<0) b2=b1;
    if (b2==b1) b2=b1+1;
    unsigned W1 = KB + ((unsigned)b1<<SH1);
    unsigned W2 = KB + ((unsigned)b2<<SH1);
    unsigned c1[4]; unsigned loc2=0;
    #pragma unroll
    for (int q=0;q<4;q++){ c1[q]=g_C[mat][t*4+q]; loc2+=c1[q]; }
    unsigned incl2 = blockScanU(loc2, ws);
    unsigned run2 = g_below2[mat] + (incl2-loc2);
    #pragma unroll
    for (int q=0;q<4;q++){
        if (c1[q]){
            if (run2<=R_LO && R_LO<run2+c1[q]){ shi[2]=t*4+q; shu[0]=run2; }
            if (run2<=R_HI && R_HI<run2+c1[q]){ shi[3]=t*4+q; shu[1]=run2; }
        }
        run2 += c1[q];
    }
    __syncthreads();
    for (int which=0; which<2; which++){
        int sq = shi[2+which];
        unsigned sr = shu[which];
        unsigned RR = which ? R_HI : R_LO;
        if (sq >= 0){
            unsigned cnt = (t<128) ? g_hist2[mat][sq*128+t] : 0u;
            unsigned icl = blockScanU(cnt, ws);
            if (t<128 && cnt){
                unsigned lo = sr + (icl-cnt);
                if (lo<=RR && RR<lo+cnt) shi[4+which] = sq*128+t;
            }
            __syncthreads();
        }
    }
    int o1=shi[4], o2=shi[5];
    if (o1<0 && o2>=0) o1=o2;
    if (o2<0 && o1>=0) o2=o1;
    if (o1<0){ o1=32768; o2=32768; }
    unsigned k1 = (o1<65536)? W1+(unsigned)o1 : W2+(unsigned)(o1-65536);
    unsigned k2 = (o2<65536)? W1+(unsigned)o2 : W2+(unsigned)(o2-65536);
    float med = 0.5f*(k2f(k1)+k2f(k2));
    return -(float)(1.4426950408889634 / (double)med);
}

// -- rowsum + in-place D->K; exp split MUFU/FMA to lift the MUFU floor -------
__global__ void k_rowsum(){
    int mat = blockIdx.y;
    __shared__ unsigned ws[32];
    __shared__ int shi[6];
    __shared__ unsigned shu[2];
    float c = compute_c(mat, ws, shi, shu);

    int bi, bj; tri_decode(blockIdx.x, bi, bj);
    int i0 = bi*128, j0 = bj*128;
    float* Dt = g_D[mat] + (size_t)blockIdx.x * TSZ;
    int warp = threadIdx.x >> 5, lane = threadIdx.x & 31;
    float ca0=0.f, ca1=0.f, ca2=0.f, ca3=0.f;
    #pragma unroll 4
    for (int it=0; it<16; it++){
        int r = warp + it*8;
        float4 d = *(float4*)&Dt[r*128 + lane*4];
        float e0=exp2f(d.x*c), e1=exp2f(d.y*c);
        float e2=exp2m(d.z*c), e3=exp2m(d.w*c);
        float4 e; e.x=e0; e.y=e1; e.z=e2; e.w=e3;
        *(float4*)&Dt[r*128 + lane*4] = e;
        float rs = (e0+e1)+(e2+e3);
        #pragma unroll
        for (int off=16; off; off>>=1) rs += __shfl_xor_sync(0xffffffffu, rs, off);
        if (lane==0) atomicAdd(&g_rowd[mat][i0+r], (double)rs);
        ca0+=e0; ca1+=e1; ca2+=e2; ca3+=e3;
    }
    {
        double ts = (double)ca0+(double)ca1+(double)ca2+(double)ca3;
        #pragma unroll
        for (int off=16; off; off>>=1) ts += __shfl_xor_sync(0xffffffffu, ts, off);
        __shared__ double sd8[8];
        if (lane==0) sd8[warp]=ts;
        __syncthreads();
        if (threadIdx.x==0){
            double s=0.0;
            for (int q=0;q<8;q++) s+=sd8[q];
            atomicAdd(&g_totd[mat], (bi==bj?1.0:2.0)*s);
        }
        __syncthreads();
    }
    if (bi != bj){
        __shared__ float cs[8][128];
        cs[warp][lane*4+0]=ca0; cs[warp][lane*4+1]=ca1;
        cs[warp][lane*4+2]=ca2; cs[warp][lane*4+3]=ca3;
        __syncthreads();
        if (threadIdx.x < 128){
            float s=0.f;
            #pragma unroll
            for (int q=0;q<8;q++) s += cs[q][threadIdx.x];
            atomicAdd(&g_rowd[mat][j0+threadIdx.x], (double)s);
        }
    }
}

// -- fused centered-product over K/L tiles (lean r12 form) -------------------
__global__ void __launch_bounds__(256) k_main(){
    int bi, bj; tri_decode(blockIdx.x, bi, bj);
    int i0 = bi*128, j0 = bj*128;
    bool diag = (bi==bj);
    int t = threadIdx.x;
    const double invn  = 1.0/(double)Nn;
    const double invn2 = invn*invn;
    float tmK = (float)(g_totd[0]*invn2);
    float tmL = (float)(g_totd[1]*invn2);

    int warp = t >> 5, lane = t & 31;
    float rmKj[4], rmLj[4];
    #pragma unroll
    for (int q=0;q<4;q++){
        rmKj[q] = (float)(__ldg(&g_rowd[0][j0+lane*4+q])*invn);
        rmLj[q] = (float)(__ldg(&g_rowd[1][j0+lane*4+q])*invn);
    }
    const float* KX = g_D[0] + (size_t)blockIdx.x * TSZ;
    const float* KY = g_D[1] + (size_t)blockIdx.x * TSZ;
    float s1=0.f, s2=0.f, s2d=0.f, trk=0.f, trl=0.f;
    #pragma unroll 2
    for (int it=0; it<8; it++){
        int r = warp + it*16;
        float4 kxa = *(const float4*)&KX[r*128 + lane*4];
        float4 kya = *(const float4*)&KY[r*128 + lane*4];
        float4 kxb = *(const float4*)&KX[(r+8)*128 + lane*4];
        float4 kyb = *(const float4*)&KY[(r+8)*128 + lane*4];
        float rmKa = (float)(__ldg(&g_rowd[0][i0+r])*invn);
        float rmLa = (float)(__ldg(&g_rowd[1][i0+r])*invn);
        float rmKb = (float)(__ldg(&g_rowd[0][i0+r+8])*invn);
        float rmLb = (float)(__ldg(&g_rowd[1][i0+r+8])*invn);
        #pragma unroll
        for (int half=0; half<2; half++){
            float4 kx = half?kxb:kxa;
            float4 ky = half?kyb:kya;
            float rmKi = half?rmKb:rmKa;
            float rmLi = half?rmLb:rmLa;
            int rr = r + half*8;
            #pragma unroll
            for (int c=0;c<4;c++){
                float k = (c==0)?kx.x:(c==1)?kx.y:(c==2)?kx.z:kx.w;
                float l = (c==0)?ky.x:(c==1)?ky.y:(c==2)?ky.z:ky.w;
                float kc = k - rmKi - rmKj[c] + tmK;
                float lc = l - rmLi - rmLj[c] + tmL;
                float pr = kc*lc;
                s1 += pr;
                float p6 = pr*(1.0f/6.0f);
                float p66 = p6*p6;
                s2 += p66;
                if (diag && rr == lane*4+c){ s2d += p66; trk += k; trl += l; }
            }
        }
    }
    double wgt = diag ? 1.0 : 2.0;
    double vals[5] = {wgt*(double)s1, wgt*(double)s2, (double)s2d, (double)trk, (double)trl};
    __shared__ double red[8][5];
    #pragma unroll
    for (int q=0;q<5;q++){
        double v = vals[q];
        #pragma unroll
        for (int off=16; off; off>>=1) v += __shfl_xor_sync(0xffffffffu, v, off);
        if (lane==0) red[warp][q]=v;
    }
    __syncthreads();
    if (t<5){
        double s=0.0;
        #pragma unroll
        for (int w=0;w<8;w++) s += red[w][t];
        g_part[t][blockIdx.x]=s;
    }
    // zero hist state for the next kernel_launch call
    int gidx = blockIdx.x*256 + t;
    for (int z = gidx; z < 2*NB2; z += TILES*256) ((unsigned*)g_hist2)[z] = 0u;
    if (gidx < 2*NB1) ((unsigned*)g_hist1)[gidx] = 0u;
    if (gidx < 2048)  ((unsigned*)g_C)[gidx] = 0u;
    if (gidx < 2){ g_below1[gidx]=0u; g_below2[gidx]=0u; }
}

__device__ double blockReduce1024(double v, double* sh){
    int t = threadIdx.x;
    sh[t]=v; __syncthreads();
    for (int off=512; off; off>>=1){
        if (t<off) sh[t]+=sh[t+off];
        __syncthreads();
    }
    double r = sh[0]; __syncthreads();
    return r;
}

// ---- final scalars + gamma quantile (Stirling lgamma + exp2f series) -------
__global__ void k_final(float* out){
    __shared__ double shD[1024];
    int t = threadIdx.x;
    double red[5];
    for (int q=0;q<5;q++){
        double s=0.0;
        for (int k=t;k<TILES;k+=1024) s += g_part[q][k];
        red[q] = blockReduce1024(s, shD);
    }
    double totK = g_totd[0], totL = g_totd[1];

    const double n = (double)Nn;
    double S1=red[0], S2=red[1], S2d=red[2], trK=red[3], trL=red[4];
    double testStat = S1/n;
    double varHSIC = (S2 - S2d)/(n*(n-1.0));
    varHSIC = varHSIC * 72.0*(n-4.0)*(n-5.0)/(n*(n-1.0)*(n-2.0)*(n-3.0));
    double muX = (totK-trK)/(n*(n-1.0));
    double muY = (totL-trL)/(n*(n-1.0));
    double mHSIC = (1.0 + muX*muY - muX - muY)/n;
    double a = mHSIC*mHSIC/varHSIC;
    double bet = varHSIC*n/mHSIC;

    const double HLN2PI = 0.918938533204672742;   // 0.5*ln(2*pi)
    const double L2E    = 1.4426950408889634;
    // lgamma(a+1+k), k = 4t..4t+3 via Stirling (one seed log per thread)
    double lgk[4];
    {
        double z   = a + 1.0 + (double)(4*t);
        double lnz = log(z);
        double r   = 1.0/z;
        #pragma unroll
        for (int q=0;q<4;q++){
            double r2 = r*r;
            lgk[q] = (z-0.5)*lnz - z + HLN2PI
                   + r*(1.0/12.0) - r2*r*(1.0/360.0);
            lnz += r - 0.5*r2 + r2*r*(1.0/3.0) - r2*r2*0.25;
            z   += 1.0;
            r    = r*(1.0 - r + r2);
            r    = r*(2.0 - z*r);
        }
    }
    double z1 = a + 1.0;
    double lnz1 = log(z1), r1 = 1.0/z1;
    double lga1 = (z1-0.5)*lnz1 - z1 + HLN2PI + r1*(1.0/12.0) - r1*r1*r1*(1.0/360.0);
    double lgA  = lga1 - log(a);

    const double p = 0.2;
    double zq = -0.8416212335729143;
    double u = 1.0 - 1.0/(9.0*a) + zq/(3.0*sqrt(a));
    double x = a*u*u*u;
    if (!(x > 1e-8)) x = 0.5*a + 1e-3;
    for (int it=0; it<2; it++){
        double lnx = log(x);
        double base = a*lnx - x;
        double loc = 0.0;
        #pragma unroll
        for (int q=0;q<4;q++){
            double e = base + (double)(4*t+q)*lnx - lgk[q];
            float f = (float)(e * L2E);
            if (f > -40.0f) loc += (double)exp2f(f);
        }
        double P = blockReduce1024(loc, shD);
        double lpdf = (a-1.0)*lnx - x - lgA;
        double pdf = exp(lpdf);
        if (pdf < 1e-300) pdf = 1e-300;
        double xn = x - (P - p)/pdf;
        if (!(xn > 0.5*x)) xn = 0.5*x;
        if (xn > 2.0*x) xn = 2.0*x;
        x = xn;
    }
    if (t==0){
        out[0] = (float)testStat;
        out[1] = (float)(bet*x);
    }
    for (int k=t; k<2*Nn; k+=1024) ((double*)g_rowd)[k]=0.0;
    if (t<2) g_totd[t]=0.0;
}

extern "C" void kernel_launch(void* const* d_in, const int* in_sizes, int n_in,
                              void* d_out, int out_size) {
    const float* X = (const float*)d_in[0];
    const float* Y = (const float*)d_in[1];
    float* out = (float*)d_out;
    (void)in_sizes; (void)n_in; (void)out_size;

    k_dist<<<dim3(TILES,2), 256>>>(X, Y);
    k_hist2<<<dim3(TILES,2), 256>>>();
    k_rowsum<<<dim3(TILES,2), 256>>>();
    k_main<<<TILES, 256>>>();                    // profile slot 4 (verify revert)
    k_final<<<1, 1024>>>(out);
}

// round 17
// speedup vs baseline: 1.5056x; 1.5056x over previous
#include <cuda_runtime.h>
#include <math.h>
#include <stdint.h>

#define Nn    4096
#define DIMS  64
#define NB1   1024
#define SH1   16
#define NB2   131072
#define KB    0xC0800000u
#define SPAN1 0x04000000u
#define R_LO 8390655u
#define R_HI 8390656u
#define TNT   32
#define TILES 528
#define TSZ   16384

__device__ float    g_D[2][TILES*TSZ];
__device__ unsigned g_hist1[2][NB1];
__device__ unsigned g_below1[2];
__device__ unsigned g_hist2[2][NB2];
__device__ unsigned g_C[2][1024];
__device__ unsigned g_below2[2];
__device__ double   g_rowd[2][Nn];
__device__ double   g_totd[2];
__device__ double   g_part[5][TILES];
__device__ unsigned g_ctr;

__device__ __forceinline__ unsigned f2k(float f){
    unsigned u = __float_as_uint(f);
    return (u & 0x80000000u) ? ~u : (u | 0x80000000u);
}
__device__ __forceinline__ float k2f(unsigned k){
    unsigned u = (k & 0x80000000u) ? (k & 0x7FFFFFFFu) : ~k;
    return __uint_as_float(u);
}
__device__ __forceinline__ void tri_decode(int q, int &bi, int &bj){
    int b = (int)((65.0 - sqrt(65.0*65.0 - 8.0*(double)q))*0.5);
    if (b > TNT-1) b = TNT-1;
    while (b*(2*TNT+1-b)/2 > q) b--;
    while ((b+1)*(2*TNT+1-(b+1))/2 <= q) b++;
    bi = b; bj = b + (q - b*(2*TNT+1-b)/2);
}

__device__ __forceinline__ void fma2(unsigned long long &d,
                                     unsigned long long a,
                                     unsigned long long b){
    asm("fma.rn.f32x2 %0, %1, %2, %3;" : "=l"(d) : "l"(a), "l"(b), "l"(d));
}
__device__ __forceinline__ unsigned long long dup2(float x){
    unsigned long long r;
    asm("mov.b64 %0, {%1, %1};" : "=l"(r) : "r"(__float_as_uint(x)));
    return r;
}

// magic-number exp2 for x in (-120, 0]; deg-7 Taylor on [-0.5,0.5], err ~5e-9
__device__ __forceinline__ float exp2m(float x){
    float t = x + 12582912.0f;
    int   r = __float_as_int(t) - 0x4B400000;
    float f = x - (t - 12582912.0f);
    float p = 1.5252734e-5f;
    p = fmaf(p, f, 1.5403530e-4f);
    p = fmaf(p, f, 1.3333558e-3f);
    p = fmaf(p, f, 9.6181291e-3f);
    p = fmaf(p, f, 5.5504109e-2f);
    p = fmaf(p, f, 2.4022651e-1f);
    p = fmaf(p, f, 6.9314718e-1f);
    p = fmaf(p, f, 1.0f);
    return p * __int_as_float((r+127)<<23);
}

__device__ __forceinline__ unsigned blockScanU(unsigned v, unsigned* ws){
    int lane = threadIdx.x & 31, warp = threadIdx.x >> 5;
    __syncthreads();
    if (threadIdx.x < 32) ws[threadIdx.x] = 0u;
    __syncthreads();
    unsigned x = v;
    #pragma unroll
    for (int off=1; off<32; off<<=1){
        unsigned y = __shfl_up_sync(0xffffffffu, x, off);
        if (lane >= off) x += y;
    }
    if (lane==31) ws[warp] = x;
    __syncthreads();
    if (warp==0){
        unsigned w = ws[lane];
        #pragma unroll
        for (int off=1; off<32; off<<=1){
            unsigned y = __shfl_up_sync(0xffffffffu, w, off);
            if (lane >= off) w += y;
        }
        ws[lane] = w;
    }
    __syncthreads();
    unsigned base = warp ? ws[warp-1] : 0u;
    return base + x;
}

// ---- distance tiles: column-paired f32x2 GEMM + fused norms + fused hist ---
__global__ void __launch_bounds__(256) k_dist(const float* __restrict__ X,
                                              const float* __restrict__ Y){
    const int mat = blockIdx.y;
    const float* A = mat ? Y : X;
    float* Dt = g_D[mat] + (size_t)blockIdx.x * TSZ;
    int bi, bj; tri_decode(blockIdx.x, bi, bj);
    int i0 = bi*128, j0 = bj*128;
    __shared__ float As[128][33];
    __shared__ float Bsk[32][130];
    __shared__ float Gi[128], Gj[128];
    __shared__ unsigned hb[NB1+1];
    int t = threadIdx.x;
    int tx = t & 15, ty = t >> 4;
    for (int b=t; b<NB1+1; b+=256) hb[b]=0u;

    unsigned long long acc2[8][4];
    #pragma unroll
    for (int a=0;a<8;a++)
        #pragma unroll
        for (int b=0;b<4;b++) acc2[a][b]=0ull;
    float nrm = 0.0f;

    for (int kk=0; kk<64; kk+=32){
        __syncthreads();
        #pragma unroll
        for (int it=0; it<4; it++){
            int l = t + it*256;
            int r = l >> 3, c4 = l & 7;
            float4 va = *(const float4*)&A[(i0+r)*DIMS + kk + c4*4];
            As[r][c4*4+0]=va.x; As[r][c4*4+1]=va.y; As[r][c4*4+2]=va.z; As[r][c4*4+3]=va.w;
            float4 vb = *(const float4*)&A[(j0+r)*DIMS + kk + c4*4];
            Bsk[c4*4+0][r]=vb.x; Bsk[c4*4+1][r]=vb.y; Bsk[c4*4+2][r]=vb.z; Bsk[c4*4+3][r]=vb.w;
        }
        __syncthreads();
        {
            float s = 0.0f;
            if (t < 128){
                #pragma unroll 8
                for (int k=0;k<32;k++){ float v = As[t][k]; s += v*v; }
            } else {
                int r = t - 128;
                #pragma unroll 8
                for (int k=0;k<32;k++){ float v = Bsk[k][r]; s += v*v; }
            }
            nrm += s;
        }
        #pragma unroll 8
        for (int k=0;k<32;k++){
            unsigned long long ad[8], bp[4];
            #pragma unroll
            for (int a=0;a<8;a++) ad[a] = dup2(As[ty+16*a][k]);
            #pragma unroll
            for (int b=0;b<4;b++)
                bp[b] = *(const unsigned long long*)&Bsk[k][2*tx + 32*b];
            #pragma unroll
            for (int a=0;a<8;a++){
                fma2(acc2[a][0], ad[a], bp[0]);
                fma2(acc2[a][1], ad[a], bp[1]);
                fma2(acc2[a][2], ad[a], bp[2]);
                fma2(acc2[a][3], ad[a], bp[3]);
            }
        }
    }
    if (t < 128) Gi[t] = nrm; else Gj[t-128] = nrm;
    __syncthreads();

    unsigned w = (bi==bj) ? 1u : 2u;
    float gi[8];
    #pragma unroll
    for (int a=0;a<8;a++) gi[a] = Gi[ty+16*a];
    #pragma unroll
    for (int a=0;a<8;a++){
        int row = ty + 16*a;
        #pragma unroll
        for (int b=0;b<4;b++){
            int col = 2*tx + 32*b;
            float dlo = __uint_as_float((unsigned)(acc2[a][b] & 0xffffffffu));
            float dhi = __uint_as_float((unsigned)(acc2[a][b] >> 32));
            float vlo = gi[a] + Gj[col]   - 2.0f*dlo;
            float vhi = gi[a] + Gj[col+1] - 2.0f*dhi;
            float2 vv; vv.x=vlo; vv.y=vhi;
            *(float2*)&Dt[row*128 + col] = vv;
            unsigned key = f2k(vlo);
            unsigned off = key - KB;
            if (off < SPAN1) atomicAdd(&hb[off>>SH1], w);
            else if (key < KB) atomicAdd(&hb[NB1], w);
            key = f2k(vhi);
            off = key - KB;
            if (off < SPAN1) atomicAdd(&hb[off>>SH1], w);
            else if (key < KB) atomicAdd(&hb[NB1], w);
        }
    }
    __syncthreads();
    for (int b=t; b<NB1; b+=256)
        if (hb[b]) atomicAdd(&g_hist1[mat][b], hb[b]);
    if (t==0 && hb[NB1]) atomicAdd(&g_below1[mat], hb[NB1]);
}

__device__ void find_windows(int mat, unsigned &W1, unsigned &W2,
                             unsigned* ws, volatile int* shB){
    int t = threadIdx.x;
    if (t==0){ shB[0]=-1; shB[1]=-1; }
    unsigned c0[4]; unsigned local=0;
    #pragma unroll
    for (int q=0;q<4;q++){ c0[q]=g_hist1[mat][t*4+q]; local+=c0[q]; }
    unsigned incl = blockScanU(local, ws);
    unsigned run = g_below1[mat] + (incl-local);
    #pragma unroll
    for (int q=0;q<4;q++){
        if (c0[q]){
            if (run<=R_LO && R_LO<run+c0[q]) shB[0]=t*4+q;
            if (run<=R_HI && R_HI<run+c0[q]) shB[1]=t*4+q;
        }
        run += c0[q];
    }
    __syncthreads();
    int b1=shB[0], b2=shB[1];
    if (b1<0) b1 = (b2>=0)? b2 : NB1/2;
    if (b2<0) b2 = b1;
    if (b2==b1) b2 = b1+1;
    W1 = KB + ((unsigned)b1 << SH1);
    W2 = KB + ((unsigned)b2 << SH1);
    __syncthreads();
}

__global__ void k_hist2(){
    int mat = blockIdx.y;
    __shared__ unsigned ws[32];
    __shared__ int shB[2];
    unsigned W1, W2;
    find_windows(mat, W1, W2, ws, shB);

    int bi, bj; tri_decode(blockIdx.x, bi, bj);
    unsigned w = (bi==bj) ? 1u : 2u;
    const float4* D4 = (const float4*)(g_D[mat] + (size_t)blockIdx.x * TSZ);
    int t = threadIdx.x;
    unsigned below = 0;
    #pragma unroll 8
    for (int it=0; it<16; it++){
        float4 d = D4[t + it*256];
        #pragma unroll
        for (int c=0;c<4;c++){
            float val = (c==0)?d.x:(c==1)?d.y:(c==2)?d.z:d.w;
            unsigned key = f2k(val);
            unsigned o1 = key - W1;
            if (o1 < 65536u){
                atomicAdd(&g_hist2[mat][o1], w);
                atomicAdd(&g_C[mat][o1>>7], w);
            } else {
                unsigned o2 = key - W2;
                if (o2 < 65536u){
                    atomicAdd(&g_hist2[mat][65536u+o2], w);
                    atomicAdd(&g_C[mat][512u+(o2>>7)], w);
                }
                else if (key < W1) below += w;
            }
        }
    }
    int lane = t & 31, warp = t >> 5;
    #pragma unroll
    for (int off=16; off; off>>=1) below += __shfl_xor_sync(0xffffffffu, below, off);
    __shared__ unsigned sb[8];
    if (lane==0) sb[warp]=below;
    __syncthreads();
    if (t==0){
        unsigned s=0;
        for (int q=0;q<8;q++) s+=sb[q];
        if (s) atomicAdd(&g_below2[mat], s);
    }
}

__device__ float compute_c(int mat, unsigned* ws, volatile int* shi,
                           volatile unsigned* shu){
    int t = threadIdx.x;
    if (t==0){ shi[0]=-1; shi[1]=-1; shi[2]=-1; shi[3]=-1; shi[4]=-1; shi[5]=-1; }
    unsigned c0[4]; unsigned loc=0;
    #pragma unroll
    for (int q=0;q<4;q++){ c0[q]=g_hist1[mat][t*4+q]; loc+=c0[q]; }
    unsigned incl = blockScanU(loc, ws);
    unsigned run = g_below1[mat] + (incl-loc);
    #pragma unroll
    for (int q=0;q<4;q++){
        if (c0[q]){
            if (run<=R_LO && R_LO<run+c0[q]) shi[0]=t*4+q;
            if (run<=R_HI && R_HI<run+c0[q]) shi[1]=t*4+q;
        }
        run += c0[q];
    }
    __syncthreads();
    int b1=shi[0], b2=shi[1];
    if (b1<0) b1=(b2>=0)?b2:NB1/2;
    if (b2<0) b2=b1;
    if (b2==b1) b2=b1+1;
    unsigned W1 = KB + ((unsigned)b1<<SH1);
    unsigned W2 = KB + ((unsigned)b2<<SH1);
    unsigned c1[4]; unsigned loc2=0;
    #pragma unroll
    for (int q=0;q<4;q++){ c1[q]=g_C[mat][t*4+q]; loc2+=c1[q]; }
    unsigned incl2 = blockScanU(loc2, ws);
    unsigned run2 = g_below2[mat] + (incl2-loc2);
    #pragma unroll
    for (int q=0;q<4;q++){
        if (c1[q]){
            if (run2<=R_LO && R_LO<run2+c1[q]){ shi[2]=t*4+q; shu[0]=run2; }
            if (run2<=R_HI && R_HI<run2+c1[q]){ shi[3]=t*4+q; shu[1]=run2; }
        }
        run2 += c1[q];
    }
    __syncthreads();
    for (int which=0; which<2; which++){
        int sq = shi[2+which];
        unsigned sr = shu[which];
        unsigned RR = which ? R_HI : R_LO;
        if (sq >= 0){
            unsigned cnt = (t<128) ? g_hist2[mat][sq*128+t] : 0u;
            unsigned icl = blockScanU(cnt, ws);
            if (t<128 && cnt){
                unsigned lo = sr + (icl-cnt);
                if (lo<=RR && RR<lo+cnt) shi[4+which] = sq*128+t;
            }
            __syncthreads();
        }
    }
    int o1=shi[4], o2=shi[5];
    if (o1<0 && o2>=0) o1=o2;
    if (o2<0 && o1>=0) o2=o1;
    if (o1<0){ o1=32768; o2=32768; }
    unsigned k1 = (o1<65536)? W1+(unsigned)o1 : W2+(unsigned)(o1-65536);
    unsigned k2 = (o2<65536)? W1+(unsigned)o2 : W2+(unsigned)(o2-65536);
    float med = 0.5f*(k2f(k1)+k2f(k2));
    return -(float)(1.4426950408889634 / (double)med);
}

// -- rowsum + in-place D->K; exp split MUFU/FMA to lift the MUFU floor -------
__global__ void k_rowsum(){
    int mat = blockIdx.y;
    __shared__ unsigned ws[32];
    __shared__ int shi[6];
    __shared__ unsigned shu[2];
    float c = compute_c(mat, ws, shi, shu);

    int bi, bj; tri_decode(blockIdx.x, bi, bj);
    int i0 = bi*128, j0 = bj*128;
    float* Dt = g_D[mat] + (size_t)blockIdx.x * TSZ;
    int warp = threadIdx.x >> 5, lane = threadIdx.x & 31;
    float ca0=0.f, ca1=0.f, ca2=0.f, ca3=0.f;
    #pragma unroll 4
    for (int it=0; it<16; it++){
        int r = warp + it*8;
        float4 d = *(float4*)&Dt[r*128 + lane*4];
        float e0=exp2f(d.x*c), e1=exp2f(d.y*c);
        float e2=exp2m(d.z*c), e3=exp2m(d.w*c);
        float4 e; e.x=e0; e.y=e1; e.z=e2; e.w=e3;
        *(float4*)&Dt[r*128 + lane*4] = e;
        float rs = (e0+e1)+(e2+e3);
        #pragma unroll
        for (int off=16; off; off>>=1) rs += __shfl_xor_sync(0xffffffffu, rs, off);
        if (lane==0) atomicAdd(&g_rowd[mat][i0+r], (double)rs);
        ca0+=e0; ca1+=e1; ca2+=e2; ca3+=e3;
    }
    {
        double ts = (double)ca0+(double)ca1+(double)ca2+(double)ca3;
        #pragma unroll
        for (int off=16; off; off>>=1) ts += __shfl_xor_sync(0xffffffffu, ts, off);
        __shared__ double sd8[8];
        if (lane==0) sd8[warp]=ts;
        __syncthreads();
        if (threadIdx.x==0){
            double s=0.0;
            for (int q=0;q<8;q++) s+=sd8[q];
            atomicAdd(&g_totd[mat], (bi==bj?1.0:2.0)*s);
        }
        __syncthreads();
    }
    if (bi != bj){
        __shared__ float cs[8][128];
        cs[warp][lane*4+0]=ca0; cs[warp][lane*4+1]=ca1;
        cs[warp][lane*4+2]=ca2; cs[warp][lane*4+3]=ca3;
        __syncthreads();
        if (threadIdx.x < 128){
            float s=0.f;
            #pragma unroll
            for (int q=0;q<8;q++) s += cs[q][threadIdx.x];
            atomicAdd(&g_rowd[mat][j0+threadIdx.x], (double)s);
        }
    }
}

__device__ double blockReduce256(double v, double* sh){
    int t = threadIdx.x;
    sh[t]=v; __syncthreads();
    for (int off=128; off; off>>=1){
        if (t<off) sh[t]+=sh[t+off];
        __syncthreads();
    }
    double r = sh[0]; __syncthreads();
    return r;
}

// ----- finalize: Temme uniform asymptotic gamma-quantile (1 thread) ---------
__device__ __noinline__ void finalize(float* out){
    __shared__ double shD[256];
    int t = threadIdx.x;
    double red[5];
    for (int q=0;q<5;q++){
        double s=0.0;
        for (int k=t;k<TILES;k+=256) s += g_part[q][k];
        red[q] = blockReduce256(s, shD);
    }
    if (t==0){
        double totK = g_totd[0], totL = g_totd[1];
        const double n = (double)Nn;
        double S1=red[0], S2=red[1], S2d=red[2], trK=red[3], trL=red[4];
        double testStat = S1/n;
        double varHSIC = (S2 - S2d)/(n*(n-1.0));
        varHSIC = varHSIC * 72.0*(n-4.0)*(n-5.0)/(n*(n-1.0)*(n-2.0)*(n-3.0));
        double muX = (totK-trK)/(n*(n-1.0));
        double muY = (totL-trL)/(n*(n-1.0));
        double mHSIC = (1.0 + muX*muY - muX - muY)/n;
        double a = mHSIC*mHSIC/varHSIC;
        double bet = varHSIC*n/mHSIC;

        const double HLN2PI = 0.918938533204672742;   // 0.5*ln(2*pi)
        double lnA = log(a);
        double ra = 1.0/a;
        double lgA = (a-0.5)*lnA - a + HLN2PI + ra*(1.0/12.0) - ra*ra*ra*(1.0/360.0);

        const double p = 0.2;                          // 1 - ALPH
        double zq = -0.8416212335729143;               // Phi^-1(0.2)
        double u = 1.0 - ra/9.0 + zq/(3.0*sqrt(a));
        double x = a*u*u*u;
        if (!(x > 1e-8)) x = 0.5*a;
        for (int it=0; it<4; it++){
            double lam = x/a;
            double s = lam - 1.0;
            double h = s - log(lam);                   // lam-1-ln(lam) >= 0
            if (h < 0.0) h = 0.0;
            double eta = sqrt(2.0*h);
            if (s < 0.0) eta = -eta;
            double c0;
            if (fabs(s) > 1e-5) c0 = 1.0/s - 1.0/eta;
            else c0 = -1.0/3.0 + s*(1.0/12.0) - s*s*(23.0/540.0);
            double pref = exp(-a*h)/sqrt(2.0*M_PI*a);  // e^{-a*eta^2/2}/sqrt(2*pi*a)
            double P = 0.5*erfc(-eta*sqrt(0.5*a)) - pref*c0;
            double lpdf = (a-1.0)*log(x) - x - lgA;
            double pdf = exp(lpdf);
            if (pdf < 1e-300) pdf = 1e-300;
            double xn = x - (P - p)/pdf;
            if (!(xn > 0.5*x)) xn = 0.5*x;
            if (xn > 2.0*x) xn = 2.0*x;
            x = xn;
        }
        out[0] = (float)testStat;
        out[1] = (float)(bet*x);
    }
    // ---- zero remaining accumulated state for the next call ----
    for (int k=t; k<2*Nn; k+=256) ((double*)g_rowd)[k]=0.0;
    if (t<2) g_totd[t]=0.0;
    if (t==0) g_ctr=0u;
}

// -- fused centered-product + last-block finalize + state-zeroing tail -------
__global__ void __launch_bounds__(256) k_main(float* out){
    int bi, bj; tri_decode(blockIdx.x, bi, bj);
    int i0 = bi*128, j0 = bj*128;
    bool diag = (bi==bj);
    int t = threadIdx.x;
    const double invn  = 1.0/(double)Nn;
    const double invn2 = invn*invn;
    float tmK = (float)(g_totd[0]*invn2);
    float tmL = (float)(g_totd[1]*invn2);

    int warp = t >> 5, lane = t & 31;
    float rmKj[4], rmLj[4];
    #pragma unroll
    for (int q=0;q<4;q++){
        rmKj[q] = (float)(__ldg(&g_rowd[0][j0+lane*4+q])*invn);
        rmLj[q] = (float)(__ldg(&g_rowd[1][j0+lane*4+q])*invn);
    }
    const float* KX = g_D[0] + (size_t)blockIdx.x * TSZ;
    const float* KY = g_D[1] + (size_t)blockIdx.x * TSZ;
    float s1=0.f, s2=0.f, s2d=0.f, trk=0.f, trl=0.f;
    #pragma unroll 2
    for (int it=0; it<8; it++){
        int r = warp + it*16;
        float4 kxa = *(const float4*)&KX[r*128 + lane*4];
        float4 kya = *(const float4*)&KY[r*128 + lane*4];
        float4 kxb = *(const float4*)&KX[(r+8)*128 + lane*4];
        float4 kyb = *(const float4*)&KY[(r+8)*128 + lane*4];
        float rmKa = (float)(__ldg(&g_rowd[0][i0+r])*invn);
        float rmLa = (float)(__ldg(&g_rowd[1][i0+r])*invn);
        float rmKb = (float)(__ldg(&g_rowd[0][i0+r+8])*invn);
        float rmLb = (float)(__ldg(&g_rowd[1][i0+r+8])*invn);
        #pragma unroll
        for (int half=0; half<2; half++){
            float4 kx = half?kxb:kxa;
            float4 ky = half?kyb:kya;
            float rmKi = half?rmKb:rmKa;
            float rmLi = half?rmLb:rmLa;
            int rr = r + half*8;
            #pragma unroll
            for (int c=0;c<4;c++){
                float k = (c==0)?kx.x:(c==1)?kx.y:(c==2)?kx.z:kx.w;
                float l = (c==0)?ky.x:(c==1)?ky.y:(c==2)?ky.z:ky.w;
                float kc = k - rmKi - rmKj[c] + tmK;
                float lc = l - rmLi - rmLj[c] + tmL;
                float pr = kc*lc;
                s1 += pr;
                float p6 = pr*(1.0f/6.0f);
                float p66 = p6*p6;
                s2 += p66;
                if (diag && rr == lane*4+c){ s2d += p66; trk += k; trl += l; }
            }
        }
    }
    double wgt = diag ? 1.0 : 2.0;
    double vals[5] = {wgt*(double)s1, wgt*(double)s2, (double)s2d, (double)trk, (double)trl};
    __shared__ double red[8][5];
    #pragma unroll
    for (int q=0;q<5;q++){
        double v = vals[q];
        #pragma unroll
        for (int off=16; off; off>>=1) v += __shfl_xor_sync(0xffffffffu, v, off);
        if (lane==0) red[warp][q]=v;
    }
    __syncthreads();
    if (t<5){
        double s=0.0;
        #pragma unroll
        for (int w=0;w<8;w++) s += red[w][t];
        atomicExch((unsigned long long*)&g_part[t][blockIdx.x],
                   __double_as_longlong(s));
    }
    // ---- zero accumulated state for the NEXT kernel_launch call ----
    int gidx = blockIdx.x*256 + t;
    for (int z = gidx; z < 2*NB2; z += TILES*256) ((unsigned*)g_hist2)[z] = 0u;
    if (gidx < 2*NB1) ((unsigned*)g_hist1)[gidx] = 0u;
    if (gidx < 2048)  ((unsigned*)g_C)[gidx] = 0u;
    if (gidx < 2){ g_below1[gidx]=0u; g_below2[gidx]=0u; }
    // ---- last-block finalize ----
    __shared__ unsigned amLast;
    __syncthreads();
    if (t==0){
        __threadfence();
        amLast = (atomicAdd(&g_ctr, 1u) == (unsigned)(TILES-1)) ? 1u : 0u;
    }
    __syncthreads();
    if (amLast) finalize(out);
}

extern "C" void kernel_launch(void* const* d_in, const int* in_sizes, int n_in,
                              void* d_out, int out_size) {
    const float* X = (const float*)d_in[0];
    const float* Y = (const float*)d_in[1];
    float* out = (float*)d_out;
    (void)in_sizes; (void)n_in; (void)out_size;

    k_dist<<<dim3(TILES,2), 256>>>(X, Y);
    k_hist2<<<dim3(TILES,2), 256>>>();
    k_rowsum<<<dim3(TILES,2), 256>>>();
    k_main<<<TILES, 256>>>(out);                 // profile slot 4
}